// round 9
// baseline (speedup 1.0000x reference)
#include <cuda_runtime.h>
#include <cuda_fp16.h>

#define NUSERS 100000
#define NITEMS 50000
#define DIM 64
#define NNODES 150001            // users + items + padding row
#define ND 9600064               // NNODES * DIM
#define NEDGES 4800000

#define SCAN_CHUNK 512
#define NB_SCAN ((NNODES + SCAN_CHUNK - 1) / SCAN_CHUNK)   // 293
#define NZERO4 ((NNODES + 3) / 4)                           // 37501 int4 stores
#define EDGE_BATCH 4
#define NEB (NEDGES / EDGE_BATCH)

// ---------------- device scratch (static allocation — allowed) -------------
__device__ int     g_idx_stride;          // 2 if int64 indices, 1 if int32
__device__ int     g_counts[NNODES + 15]; // row degrees
__device__ int     g_rowptr[NNODES];      // row start slots (non-monotonic ok)
__device__ int     g_cursor[NNODES];      // scatter cursors
__device__ int     g_total;               // block-base reservation counter
__device__ int2    g_edges[NEDGES];       // packed CSR records: col, bits(val)
__device__ __half2 g_mir0[ND / 2];        // fp16 feature mirror, ping
__device__ __half2 g_mir1[ND / 2];        // fp16 feature mirror, pong

// ---------------------------------------------------------------------------
// Launch 0: zero counters + total + (thread 0) detect index width.
// ---------------------------------------------------------------------------
__global__ void gcn_zero_detect(const int* __restrict__ rows32,
                                const int* __restrict__ cols32) {
    int i = blockIdx.x * blockDim.x + threadIdx.x;
    if (i < NZERO4)
        reinterpret_cast<int4*>(g_counts)[i] = make_int4(0, 0, 0, 0);
    if (i == 0) {
        g_total = 0;
        bool is64 = true;
        #pragma unroll
        for (int k = 0; k < 16; k++) {
            if (rows32[2 * k + 1] != 0) is64 = false;
            if (cols32[2 * k + 1] != 0) is64 = false;
        }
        g_idx_stride = is64 ? 2 : 1;
    }
}

// ---------------------------------------------------------------------------
// Launch 1: histogram of row degrees (4 edges/thread).
// ---------------------------------------------------------------------------
__global__ void gcn_hist_kernel(const int* __restrict__ rowsw) {
    int t = blockIdx.x * blockDim.x + threadIdx.x;
    if (t >= NEB) return;
    int e = t * EDGE_BATCH;
    int stride = g_idx_stride;
    int r0 = rowsw[(e + 0) * stride];
    int r1 = rowsw[(e + 1) * stride];
    int r2 = rowsw[(e + 2) * stride];
    int r3 = rowsw[(e + 3) * stride];
    atomicAdd(&g_counts[r0], 1);
    atomicAdd(&g_counts[r1], 1);
    atomicAdd(&g_counts[r2], 1);
    atomicAdd(&g_counts[r3], 1);
}

// ---------------------------------------------------------------------------
// Launch 2: fused scan (block scan + atomic base reservation).
// ---------------------------------------------------------------------------
__global__ void gcn_scan_fused(void) {
    __shared__ int s[SCAN_CHUNK];
    __shared__ int base_sh;
    int t = threadIdx.x;
    int i = blockIdx.x * SCAN_CHUNK + t;
    int x = (i < NNODES) ? g_counts[i] : 0;
    s[t] = x;
    __syncthreads();
    for (int off = 1; off < SCAN_CHUNK; off <<= 1) {
        int v = (t >= off) ? s[t - off] : 0;
        __syncthreads();
        s[t] += v;
        __syncthreads();
    }
    if (t == SCAN_CHUNK - 1)
        base_sh = atomicAdd(&g_total, s[SCAN_CHUNK - 1]);
    __syncthreads();
    if (i < NNODES) {
        int start = base_sh + s[t] - x;
        g_rowptr[i] = start;
        g_cursor[i] = start;
    }
}

// ---------------------------------------------------------------------------
// Launch 3: scatter edges into packed CSR slots.
// ---------------------------------------------------------------------------
__global__ void gcn_scatter_kernel(const int* __restrict__ rowsw,
                                   const int* __restrict__ colsw,
                                   const float* __restrict__ vals) {
    int t = blockIdx.x * blockDim.x + threadIdx.x;
    if (t >= NEB) return;
    int e = t * EDGE_BATCH;
    int stride = g_idx_stride;

    int r0 = rowsw[(e + 0) * stride];
    int r1 = rowsw[(e + 1) * stride];
    int r2 = rowsw[(e + 2) * stride];
    int r3 = rowsw[(e + 3) * stride];
    int c0 = colsw[(e + 0) * stride];
    int c1 = colsw[(e + 1) * stride];
    int c2 = colsw[(e + 2) * stride];
    int c3 = colsw[(e + 3) * stride];
    float4 v = *reinterpret_cast<const float4*>(vals + e);

    int p0 = atomicAdd(&g_cursor[r0], 1);
    int p1 = atomicAdd(&g_cursor[r1], 1);
    int p2 = atomicAdd(&g_cursor[r2], 1);
    int p3 = atomicAdd(&g_cursor[r3], 1);

    g_edges[p0] = make_int2(c0, __float_as_int(v.x));
    g_edges[p1] = make_int2(c1, __float_as_int(v.y));
    g_edges[p2] = make_int2(c2, __float_as_int(v.z));
    g_edges[p3] = make_int2(c3, __float_as_int(v.w));
}

// ---------------------------------------------------------------------------
// Launch 4: ego = concat(user_emb, item_emb) in f32 + fp16 mirror (ping).
// ---------------------------------------------------------------------------
__global__ void gcn_init_kernel(const float4* __restrict__ user_emb,
                                const float4* __restrict__ item_emb,
                                float4* __restrict__ ego) {
    const int n4 = ND / 4;
    const int u4 = NUSERS * (DIM / 4);
    int i = blockIdx.x * blockDim.x + threadIdx.x;
    if (i < n4) {
        float4 v = (i < u4) ? user_emb[i] : item_emb[i - u4];
        ego[i] = v;
        g_mir0[2 * i + 0] = __floats2half2_rn(v.x, v.y);
        g_mir0[2 * i + 1] = __floats2half2_rn(v.z, v.w);
    }
}

// ---------------------------------------------------------------------------
// Launches 5-7: CSR SpMM gathering from the fp16 mirror (128B/edge instead
// of 256B), fp32 accumulation, f32 output + fp16 mirror output (ping-pong).
// FUSE variant emits hsum = ego + h1 + h2 + h3 and skips the mirror write.
// ---------------------------------------------------------------------------
template <bool FUSE>
__global__ void __launch_bounds__(256)
gcn_spmm_h(int srcSel,
           float* __restrict__ y,
           const float* __restrict__ ego,
           const float* __restrict__ h1,
           const float* __restrict__ h2,
           float* __restrict__ hsum) {
    int warp = (blockIdx.x * blockDim.x + threadIdx.x) >> 5;
    if (warp >= NNODES) return;
    int lane = threadIdx.x & 31;

    const __half2* __restrict__ hin  = srcSel ? g_mir1 : g_mir0;
    __half2* __restrict__       hout = srcSel ? g_mir0 : g_mir1;

    int start = __ldg(&g_rowptr[warp]);
    int end   = start + __ldg(&g_counts[warp]);

    float ax = 0.f, ay = 0.f;
    int i = start;
    for (; i + 4 <= end; i += 4) {
        int2 e0 = g_edges[i];
        int2 e1 = g_edges[i + 1];
        int2 e2 = g_edges[i + 2];
        int2 e3 = g_edges[i + 3];
        __half2 q0 = hin[e0.x * 32 + lane];
        __half2 q1 = hin[e1.x * 32 + lane];
        __half2 q2 = hin[e2.x * 32 + lane];
        __half2 q3 = hin[e3.x * 32 + lane];
        float2 g0 = __half22float2(q0);
        float2 g1 = __half22float2(q1);
        float2 g2 = __half22float2(q2);
        float2 g3 = __half22float2(q3);
        float v0 = __int_as_float(e0.y), v1 = __int_as_float(e1.y);
        float v2 = __int_as_float(e2.y), v3 = __int_as_float(e3.y);
        ax += v0 * g0.x + v1 * g1.x + v2 * g2.x + v3 * g3.x;
        ay += v0 * g0.y + v1 * g1.y + v2 * g2.y + v3 * g3.y;
    }
    for (; i < end; i++) {
        int2 e0 = g_edges[i];
        float2 g0 = __half22float2(hin[e0.x * 32 + lane]);
        float v0 = __int_as_float(e0.y);
        ax += v0 * g0.x;
        ay += v0 * g0.y;
    }

    size_t base = (size_t)warp * DIM + lane * 2;
    *reinterpret_cast<float2*>(y + base) = make_float2(ax, ay);

    if (FUSE) {
        float2 a = *reinterpret_cast<const float2*>(ego + base);
        float2 b = *reinterpret_cast<const float2*>(h1 + base);
        float2 c = *reinterpret_cast<const float2*>(h2 + base);
        *reinterpret_cast<float2*>(hsum + base) =
            make_float2(a.x + b.x + c.x + ax, a.y + b.y + c.y + ay);
    } else {
        hout[warp * 32 + lane] = __floats2half2_rn(ax, ay);
    }
}

// ---------------------------------------------------------------------------
// kernel_launch — graph-capturable, allocation-free.
// Output layout (out_size = 5*ND): [h_sum | ego | h1 | h2 | h3]
// ---------------------------------------------------------------------------
extern "C" void kernel_launch(void* const* d_in, const int* in_sizes, int n_in,
                              void* d_out, int out_size) {
    const float* user_emb = (const float*)d_in[0];
    const float* item_emb = (const float*)d_in[1];
    const float* vals     = (const float*)d_in[2];
    const int*   rowsw    = (const int*)d_in[3];
    const int*   colsw    = (const int*)d_in[4];

    float* out  = (float*)d_out;
    float* hsum = out;
    float* ego  = out + (size_t)ND;
    float* h1   = out + (size_t)2 * ND;
    float* h2   = out + (size_t)3 * ND;
    float* h3   = out + (size_t)4 * ND;

    // 0
    gcn_zero_detect<<<(NZERO4 + 255) / 256, 256>>>(rowsw, colsw);
    // 1
    gcn_hist_kernel<<<(NEB + 255) / 256, 256>>>(rowsw);
    // 2
    gcn_scan_fused<<<NB_SCAN, SCAN_CHUNK>>>();
    // 3
    gcn_scatter_kernel<<<(NEB + 255) / 256, 256>>>(rowsw, colsw, vals);
    // 4
    {
        const int n4 = ND / 4;
        gcn_init_kernel<<<(n4 + 255) / 256, 256>>>(
            (const float4*)user_emb, (const float4*)item_emb, (float4*)ego);
    }
    // 5-7  (ncu -s 5 profiles layer-1 SpMM)
    {
        long long threads = (long long)NNODES * 32;
        unsigned grd = (unsigned)((threads + 255) / 256);
        gcn_spmm_h<false><<<grd, 256>>>(0, h1, nullptr, nullptr, nullptr,
                                        nullptr);   // mir0 -> h1, mir1
        gcn_spmm_h<false><<<grd, 256>>>(1, h2, nullptr, nullptr, nullptr,
                                        nullptr);   // mir1 -> h2, mir0
        gcn_spmm_h<true><<<grd, 256>>>(0, h3, ego, h1, h2, hsum);  // mir0 -> h3
    }
}

// round 10
// speedup vs baseline: 1.0391x; 1.0391x over previous
#include <cuda_runtime.h>
#include <cuda_fp16.h>

#define NUSERS 100000
#define NITEMS 50000
#define DIM 64
#define NNODES 150001            // users + items + padding row
#define ND 9600064               // NNODES * DIM
#define NEDGES 4800000

#define SCAN_CHUNK 512
#define NB_SCAN ((NNODES + SCAN_CHUNK - 1) / SCAN_CHUNK)   // 293
#define NZERO4 ((NNODES + 3) / 4)                           // 37501 int4 stores
#define EDGE_BATCH 4
#define NEB (NEDGES / EDGE_BATCH)

// ---------------- device scratch (static allocation — allowed) -------------
__device__ int     g_idx_stride;          // 2 if int64 indices, 1 if int32
__device__ int     g_counts[NNODES + 15]; // row degrees
__device__ int     g_rowptr[NNODES];      // row start slots (non-monotonic ok)
__device__ int     g_cursor[NNODES];      // scatter cursors
__device__ int     g_total;               // block-base reservation counter
__device__ int2    g_edges[NEDGES];       // packed CSR records: col, bits(val)
__device__ __half2 g_mir0[ND / 2];        // fp16 feature mirror, ping
__device__ __half2 g_mir1[ND / 2];        // fp16 feature mirror, pong

// ---------------------------------------------------------------------------
// Launch 0: zero counters + total + (thread 0) detect index width.
// ---------------------------------------------------------------------------
__global__ void gcn_zero_detect(const int* __restrict__ rows32,
                                const int* __restrict__ cols32) {
    int i = blockIdx.x * blockDim.x + threadIdx.x;
    if (i < NZERO4)
        reinterpret_cast<int4*>(g_counts)[i] = make_int4(0, 0, 0, 0);
    if (i == 0) {
        g_total = 0;
        bool is64 = true;
        #pragma unroll
        for (int k = 0; k < 16; k++) {
            if (rows32[2 * k + 1] != 0) is64 = false;
            if (cols32[2 * k + 1] != 0) is64 = false;
        }
        g_idx_stride = is64 ? 2 : 1;
    }
}

// ---------------------------------------------------------------------------
// Launch 1: ego = concat(user_emb, item_emb) in f32 + fp16 mirror (ping).
// ---------------------------------------------------------------------------
__global__ void gcn_init_kernel(const float4* __restrict__ user_emb,
                                const float4* __restrict__ item_emb,
                                float4* __restrict__ ego) {
    const int n4 = ND / 4;
    const int u4 = NUSERS * (DIM / 4);
    int i = blockIdx.x * blockDim.x + threadIdx.x;
    if (i < n4) {
        float4 v = (i < u4) ? user_emb[i] : item_emb[i - u4];
        ego[i] = v;
        g_mir0[2 * i + 0] = __floats2half2_rn(v.x, v.y);
        g_mir0[2 * i + 1] = __floats2half2_rn(v.z, v.w);
    }
}

// ---------------------------------------------------------------------------
// Launch 2: histogram of row degrees (4 edges/thread).
// ---------------------------------------------------------------------------
__global__ void gcn_hist_kernel(const int* __restrict__ rowsw) {
    int t = blockIdx.x * blockDim.x + threadIdx.x;
    if (t >= NEB) return;
    int e = t * EDGE_BATCH;
    int stride = g_idx_stride;
    int r0 = rowsw[(e + 0) * stride];
    int r1 = rowsw[(e + 1) * stride];
    int r2 = rowsw[(e + 2) * stride];
    int r3 = rowsw[(e + 3) * stride];
    atomicAdd(&g_counts[r0], 1);
    atomicAdd(&g_counts[r1], 1);
    atomicAdd(&g_counts[r2], 1);
    atomicAdd(&g_counts[r3], 1);
}

// ---------------------------------------------------------------------------
// Launch 3: fused scan (block scan + atomic base reservation).
// ---------------------------------------------------------------------------
__global__ void gcn_scan_fused(void) {
    __shared__ int s[SCAN_CHUNK];
    __shared__ int base_sh;
    int t = threadIdx.x;
    int i = blockIdx.x * SCAN_CHUNK + t;
    int x = (i < NNODES) ? g_counts[i] : 0;
    s[t] = x;
    __syncthreads();
    for (int off = 1; off < SCAN_CHUNK; off <<= 1) {
        int v = (t >= off) ? s[t - off] : 0;
        __syncthreads();
        s[t] += v;
        __syncthreads();
    }
    if (t == SCAN_CHUNK - 1)
        base_sh = atomicAdd(&g_total, s[SCAN_CHUNK - 1]);
    __syncthreads();
    if (i < NNODES) {
        int start = base_sh + s[t] - x;
        g_rowptr[i] = start;
        g_cursor[i] = start;
    }
}

// ---------------------------------------------------------------------------
// Launch 4: scatter edges into packed CSR slots.
// ---------------------------------------------------------------------------
__global__ void gcn_scatter_kernel(const int* __restrict__ rowsw,
                                   const int* __restrict__ colsw,
                                   const float* __restrict__ vals) {
    int t = blockIdx.x * blockDim.x + threadIdx.x;
    if (t >= NEB) return;
    int e = t * EDGE_BATCH;
    int stride = g_idx_stride;

    int r0 = rowsw[(e + 0) * stride];
    int r1 = rowsw[(e + 1) * stride];
    int r2 = rowsw[(e + 2) * stride];
    int r3 = rowsw[(e + 3) * stride];
    int c0 = colsw[(e + 0) * stride];
    int c1 = colsw[(e + 1) * stride];
    int c2 = colsw[(e + 2) * stride];
    int c3 = colsw[(e + 3) * stride];
    float4 v = *reinterpret_cast<const float4*>(vals + e);

    int p0 = atomicAdd(&g_cursor[r0], 1);
    int p1 = atomicAdd(&g_cursor[r1], 1);
    int p2 = atomicAdd(&g_cursor[r2], 1);
    int p3 = atomicAdd(&g_cursor[r3], 1);

    g_edges[p0] = make_int2(c0, __float_as_int(v.x));
    g_edges[p1] = make_int2(c1, __float_as_int(v.y));
    g_edges[p2] = make_int2(c2, __float_as_int(v.z));
    g_edges[p3] = make_int2(c3, __float_as_int(v.w));
}

// ---------------------------------------------------------------------------
// Launches 5-7: CSR SpMM, lane-parallel edge fetch + shfl broadcast.
// Each lane loads one edge record (coalesced), then 32 gathers issue
// back-to-back (MLP ~32, no per-edge L2 round trip in the chain).
// fp16 mirror gathers, fp32 accumulation, dual accumulators.
// ---------------------------------------------------------------------------
template <bool FUSE>
__global__ void __launch_bounds__(256)
gcn_spmm_h(int srcSel,
           float* __restrict__ y,
           const float* __restrict__ ego,
           const float* __restrict__ h1,
           const float* __restrict__ h2,
           float* __restrict__ hsum) {
    int warp = (blockIdx.x * blockDim.x + threadIdx.x) >> 5;
    if (warp >= NNODES) return;
    int lane = threadIdx.x & 31;

    const __half2* __restrict__ hin  = srcSel ? g_mir1 : g_mir0;
    __half2* __restrict__       hout = srcSel ? g_mir0 : g_mir1;

    int start = __ldg(&g_rowptr[warp]);
    int cnt   = __ldg(&g_counts[warp]);

    float ax = 0.f, ay = 0.f, bx = 0.f, by = 0.f;

    for (int base = 0; base < cnt; base += 32) {
        int rem = cnt - base;
        // lane-parallel edge fetch (one coalesced wavefront per 32 edges)
        int2 my = (lane < rem) ? g_edges[start + base + lane]
                               : make_int2(NNODES - 1, 0);  // pad: val 0
        if (rem >= 32) {
            #pragma unroll
            for (int k = 0; k < 32; k += 2) {
                int   ca = __shfl_sync(0xffffffffu, my.x, k);
                float va = __int_as_float(__shfl_sync(0xffffffffu, my.y, k));
                int   cb = __shfl_sync(0xffffffffu, my.x, k + 1);
                float vb = __int_as_float(__shfl_sync(0xffffffffu, my.y, k + 1));
                float2 ga = __half22float2(hin[ca * 32 + lane]);
                float2 gb = __half22float2(hin[cb * 32 + lane]);
                ax += va * ga.x; ay += va * ga.y;
                bx += vb * gb.x; by += vb * gb.y;
            }
        } else {
            for (int k = 0; k < rem; k++) {
                int   ca = __shfl_sync(0xffffffffu, my.x, k);
                float va = __int_as_float(__shfl_sync(0xffffffffu, my.y, k));
                float2 ga = __half22float2(hin[ca * 32 + lane]);
                ax += va * ga.x; ay += va * ga.y;
            }
        }
    }
    ax += bx; ay += by;

    size_t base_o = (size_t)warp * DIM + lane * 2;
    *reinterpret_cast<float2*>(y + base_o) = make_float2(ax, ay);

    if (FUSE) {
        float2 a = *reinterpret_cast<const float2*>(ego + base_o);
        float2 b = *reinterpret_cast<const float2*>(h1 + base_o);
        float2 c = *reinterpret_cast<const float2*>(h2 + base_o);
        *reinterpret_cast<float2*>(hsum + base_o) =
            make_float2(a.x + b.x + c.x + ax, a.y + b.y + c.y + ay);
    } else {
        hout[warp * 32 + lane] = __floats2half2_rn(ax, ay);
    }
}

// ---------------------------------------------------------------------------
// kernel_launch — graph-capturable, allocation-free.
// Output layout (out_size = 5*ND): [h_sum | ego | h1 | h2 | h3]
// ---------------------------------------------------------------------------
extern "C" void kernel_launch(void* const* d_in, const int* in_sizes, int n_in,
                              void* d_out, int out_size) {
    const float* user_emb = (const float*)d_in[0];
    const float* item_emb = (const float*)d_in[1];
    const float* vals     = (const float*)d_in[2];
    const int*   rowsw    = (const int*)d_in[3];
    const int*   colsw    = (const int*)d_in[4];

    float* out  = (float*)d_out;
    float* hsum = out;
    float* ego  = out + (size_t)ND;
    float* h1   = out + (size_t)2 * ND;
    float* h2   = out + (size_t)3 * ND;
    float* h3   = out + (size_t)4 * ND;

    // 0
    gcn_zero_detect<<<(NZERO4 + 255) / 256, 256>>>(rowsw, colsw);
    // 1 (independent of build; placed early so SpMM lands at sample index)
    {
        const int n4 = ND / 4;
        gcn_init_kernel<<<(n4 + 255) / 256, 256>>>(
            (const float4*)user_emb, (const float4*)item_emb, (float4*)ego);
    }
    // 2
    gcn_hist_kernel<<<(NEB + 255) / 256, 256>>>(rowsw);
    // 3
    gcn_scan_fused<<<NB_SCAN, SCAN_CHUNK>>>();
    // 4
    gcn_scatter_kernel<<<(NEB + 255) / 256, 256>>>(rowsw, colsw, vals);
    // 5-7
    {
        long long threads = (long long)NNODES * 32;
        unsigned grd = (unsigned)((threads + 255) / 256);
        gcn_spmm_h<false><<<grd, 256>>>(0, h1, nullptr, nullptr, nullptr,
                                        nullptr);   // mir0 -> h1, mir1
        gcn_spmm_h<false><<<grd, 256>>>(1, h2, nullptr, nullptr, nullptr,
                                        nullptr);   // mir1 -> h2, mir0
        gcn_spmm_h<true><<<grd, 256>>>(0, h3, ego, h1, h2, hsum);  // mir0 -> h3
    }
}